// round 16
// baseline (speedup 1.0000x reference)
#include <cuda_runtime.h>
#include <cuda_fp16.h>
#include <cstdint>
#include <math.h>

#define BATCH 16
#define CIN   64
#define LEN   1024
#define HID   1024
#define OUTC  512
#define EPS   1e-5f
#define MTOT  (BATCH*LEN)   // 16384

// KAN GEMM tiling (R9 best): CTA 128x128, KC=32, 2-stage, 2 CTAs/SM, persistent tiles
#define KC     32
#define NK     (HID/KC)      // 32
#define A_ST   24576
#define B_ST   24576
#define STG    (A_ST + B_ST) // 49152
#define SMEM_GEMM (2*STG)    // 98304
#define PROJ_SMEM 67584
#define PRS 132
#define PERSIST_CTAS 296     // 2 per SM x 148 SMs

// ---------------- scratch ----------------
__device__ __align__(16)  __half g_h1h[MTOT*HID];
__device__ __align__(16)  __half g_h2h[MTOT*OUTC];
__device__ __align__(128) __half g_A3a[(size_t)MTOT*3072];
__device__ __align__(128) __half g_A3b[(size_t)MTOT*3072];
__device__ __align__(128) __half g_B3a[(size_t)3*HID*1024];
__device__ __align__(128) __half g_B3b[(size_t)3*OUTC*1024];
__device__ __align__(128) __half g_xh[(size_t)MTOT*64];
__device__ __align__(128) __half g_wh[(size_t)HID*64];
__device__ float g_c01[HID];
__device__ float g_c02[OUTC];
__device__ float g_part[BATCH*8*OUTC];

// ---------------- helpers ----------------
__device__ __forceinline__ uint32_t smem_u32(const void* p) {
    uint32_t a;
    asm("{ .reg .u64 t; cvta.to.shared.u64 t, %1; cvt.u32.u64 %0, t; }" : "=r"(a) : "l"(p));
    return a;
}

#define LDSM_X4(r, addr) \
    asm volatile("ldmatrix.sync.aligned.m8n8.x4.shared.b16 {%0,%1,%2,%3}, [%4];" \
        : "=r"((r)[0]), "=r"((r)[1]), "=r"((r)[2]), "=r"((r)[3]) : "r"(addr))
#define MMA16816(d, a, b) \
    asm volatile("mma.sync.aligned.m16n8k16.row.col.f32.f16.f16.f32 " \
        "{%0,%1,%2,%3}, {%4,%5,%6,%7}, {%8,%9}, {%0,%1,%2,%3};" \
        : "+f"((d)[0]), "+f"((d)[1]), "+f"((d)[2]), "+f"((d)[3]) \
        : "r"((a)[0]), "r"((a)[1]), "r"((a)[2]), "r"((a)[3]), "r"((b)[0]), "r"((b)[1]))

// ---------------- fused prep: xconv | wconv | repackB1 | repackB2 ----------------
__global__ void prep_kernel(const float* __restrict__ x, const float* __restrict__ W,
                            const float* __restrict__ coeffs1, const float* __restrict__ bias1,
                            const float* __restrict__ coeffs2, const float* __restrict__ bias2) {
    __shared__ __align__(16) char sbuf[64 * 129 * 4];
    int blk = blockIdx.x;
    int tid = threadIdx.x;

    if (blk < 128) {                         // xconv
        float (*tile)[129] = reinterpret_cast<float(*)[129]>(sbuf);
        int b = blk >> 3, l0 = (blk & 7) * 128;
        #pragma unroll
        for (int i = 0; i < 32; i++) {
            int idx = tid + i * 256;
            int c = idx >> 7, l = idx & 127;
            tile[c][l] = x[((size_t)b * CIN + c) * LEN + l0 + l];
        }
        __syncthreads();
        #pragma unroll
        for (int i = 0; i < 4; i++) {
            int idx = tid + i * 256;
            int l = idx >> 3, q = idx & 7;
            __half2 h[4];
            #pragma unroll
            for (int j = 0; j < 4; j++) {
                int c = q * 8 + j * 2;
                h[j] = __half2(__float2half_rn(tile[c][l]), __float2half_rn(tile[c + 1][l]));
            }
            *reinterpret_cast<uint4*>(g_xh + ((size_t)(b * LEN + l0 + l)) * 64 + q * 8) =
                *reinterpret_cast<uint4*>(h);
        }
    } else if (blk < 136) {                  // wconv
        float (*tile)[129] = reinterpret_cast<float(*)[129]>(sbuf);
        int n0 = (blk - 128) * 128;
        #pragma unroll
        for (int i = 0; i < 32; i++) {
            int idx = tid + i * 256;
            int k = idx >> 7, n = idx & 127;
            tile[k][n] = W[(size_t)k * HID + n0 + n];
        }
        __syncthreads();
        #pragma unroll
        for (int i = 0; i < 4; i++) {
            int idx = tid + i * 256;
            int n = idx >> 3, q = idx & 7;
            __half2 h[4];
            #pragma unroll
            for (int j = 0; j < 4; j++) {
                int k = q * 8 + j * 2;
                h[j] = __half2(__float2half_rn(tile[k][n]), __float2half_rn(tile[k + 1][n]));
            }
            *reinterpret_cast<uint4*>(g_wh + ((size_t)(n0 + n)) * 64 + q * 8) =
                *reinterpret_cast<uint4*>(h);
        }
    } else {                                 // repackB
        int o; int N; __half* B3; float* c0;
        const float* coeffs; const float* bias;
        if (blk < 136 + HID) {
            o = blk - 136;        N = HID;  B3 = g_B3a; c0 = g_c01; coeffs = coeffs1; bias = bias1;
        } else {
            o = blk - 136 - HID;  N = OUTC; B3 = g_B3b; c0 = g_c02; coeffs = coeffs2; bias = bias2;
        }
        float* red = reinterpret_cast<float*>(sbuf);
        float s = 0.f;
        #pragma unroll
        for (int it = 0; it < 4; it++) {
            int c = tid + it * 256;
            float4 v = *reinterpret_cast<const float4*>(coeffs + ((size_t)o * HID + c) * 4);
            s += v.x;
            size_t base = (size_t)o * 1024 + c;
            size_t ps = (size_t)N * 1024;
            B3[0*ps + base] = __float2half_rn(v.y);
            B3[1*ps + base] = __float2half_rn(v.z);
            B3[2*ps + base] = __float2half_rn(v.w);
        }
        red[tid] = s; __syncthreads();
        #pragma unroll
        for (int st = 128; st > 0; st >>= 1) {
            if (tid < st) red[tid] += red[tid + st];
            __syncthreads();
        }
        if (tid == 0) c0[o] = red[0] + bias[o];
    }
}

// ---------------- projection GEMM on tensor cores + staged coalesced split ----------------
__global__ void __launch_bounds__(256, 2) gemm_proj_tc(const float* __restrict__ bias) {
    extern __shared__ char smem[];
    uint32_t sA = smem_u32(smem);
    uint32_t sB = sA + 16384;
    int tid = threadIdx.x, lane = tid & 31, w = tid >> 5;
    int wm = w >> 1, wn = w & 1;
    int m0 = blockIdx.y * 128, n0 = blockIdx.x * 128;

    #pragma unroll
    for (int i = 0; i < 4; i++) {
        int idx = tid + i * 256;
        int row = idx >> 3, ch = idx & 7;
        const void* gp = (const void*)(g_xh + (size_t)(m0 + row) * 64 + ch * 8);
        uint32_t sp = sA + row * 128 + ((uint32_t)(ch ^ (row & 7)) << 4);
        asm volatile("cp.async.cg.shared.global [%0], [%1], 16;" :: "r"(sp), "l"(gp));
    }
    #pragma unroll
    for (int i = 0; i < 4; i++) {
        int idx = tid + i * 256;
        int row = idx >> 3, ch = idx & 7;
        const void* gp = (const void*)(g_wh + (size_t)(n0 + row) * 64 + ch * 8);
        uint32_t sp = sB + row * 128 + ((uint32_t)(ch ^ (row & 7)) << 4);
        asm volatile("cp.async.cg.shared.global [%0], [%1], 16;" :: "r"(sp), "l"(gp));
    }
    asm volatile("cp.async.commit_group;" ::: "memory");
    asm volatile("cp.async.wait_group 0;" ::: "memory");
    __syncthreads();

    float acc[2][8][4] = {};
    int hiA = lane >> 4;
    uint32_t aOff[2]; int aSw[2];
    #pragma unroll
    for (int s = 0; s < 2; s++) {
        int r = wm * 32 + s * 16 + (lane & 15);
        aOff[s] = (uint32_t)r * 128; aSw[s] = r & 7;
    }
    uint32_t offB[2][8];
    #pragma unroll
    for (int grp = 0; grp < 2; grp++) {
        int c = (lane >> 3) + grp * 4;
        int rr = lane & 7;
        #pragma unroll
        for (int t = 0; t < 8; t++) {
            int r = wn * 64 + t * 8 + rr;
            offB[grp][t] = (uint32_t)r * 128 + ((uint32_t)(c ^ (r & 7)) << 4);
        }
    }

    #pragma unroll
    for (int grp = 0; grp < 2; grp++) {
        uint32_t bq[8][4];
        #pragma unroll
        for (int t = 0; t < 8; t++)
            LDSM_X4(bq[t], sB + offB[grp][t]);
        #pragma unroll
        for (int kp = 0; kp < 2; kp++) {
            int kk = grp * 2 + kp;
            #pragma unroll
            for (int s = 0; s < 2; s++) {
                uint32_t ah[4];
                LDSM_X4(ah, sA + aOff[s] + ((uint32_t)((kk * 2 + hiA) ^ aSw[s]) << 4));
                #pragma unroll
                for (int t = 0; t < 8; t++)
                    MMA16816(acc[s][t], ah, &bq[t][kp * 2]);
            }
        }
    }

    __syncthreads();
    float* tile = reinterpret_cast<float*>(smem);
    #pragma unroll
    for (int t = 0; t < 8; t++) {
        int col = wn * 64 + t * 8 + (lane & 3) * 2;
        #pragma unroll
        for (int s = 0; s < 2; s++) {
            int r0 = wm * 32 + s * 16 + (lane >> 2);
            *reinterpret_cast<float2*>(tile + (size_t)r0 * PRS + col) =
                make_float2(acc[s][t][0], acc[s][t][1]);
            *reinterpret_cast<float2*>(tile + (size_t)(r0 + 8) * PRS + col) =
                make_float2(acc[s][t][2], acc[s][t][3]);
        }
    }
    __syncthreads();

    int row = tid >> 1, half = tid & 1;
    const float* src = tile + (size_t)row * PRS + half * 64;
    const float* bsrc = bias + n0 + half * 64;
    __half* dst = g_A3a + (size_t)(m0 + row) * 3072 + n0 + half * 64;
    #pragma unroll
    for (int q = 0; q < 8; q++) {
        float4 v0 = *reinterpret_cast<const float4*>(src + q * 8);
        float4 v1 = *reinterpret_cast<const float4*>(src + q * 8 + 4);
        float4 b0 = *reinterpret_cast<const float4*>(bsrc + q * 8);
        float4 b1 = *reinterpret_cast<const float4*>(bsrc + q * 8 + 4);
        float hv[8] = {v0.x + b0.x, v0.y + b0.y, v0.z + b0.z, v0.w + b0.w,
                       v1.x + b1.x, v1.y + b1.y, v1.z + b1.z, v1.w + b1.w};
        __half2 p1[4], p2[4], p3[4];
        #pragma unroll
        for (int j = 0; j < 4; j++) {
            float a = hv[2*j], b = hv[2*j+1];
            float a2 = a * a, b2 = b * b;
            p1[j] = __half2(__float2half_rn(a),     __float2half_rn(b));
            p2[j] = __half2(__float2half_rn(a2),    __float2half_rn(b2));
            p3[j] = __half2(__float2half_rn(a2*a),  __float2half_rn(b2*b));
        }
        *reinterpret_cast<uint4*>(dst + q * 8)        = *reinterpret_cast<uint4*>(p1);
        *reinterpret_cast<uint4*>(dst + 1024 + q * 8) = *reinterpret_cast<uint4*>(p2);
        *reinterpret_cast<uint4*>(dst + 2048 + q * 8) = *reinterpret_cast<uint4*>(p3);
    }
}

// ---------------- LN + exact GELU + fp16 power split (shfl LN, 128 thr/row) ----------------
__global__ void __launch_bounds__(128) ln_gelu_split_kernel(const float* __restrict__ g,
                                                            const float* __restrict__ beta) {
    __shared__ float red[8];
    int t = threadIdx.x;
    int lane = t & 31, w = t >> 5;
    const __half* p = g_h1h + (size_t)blockIdx.x * HID + t * 8;
    __half2 hv[4];
    *reinterpret_cast<uint4*>(hv) = *reinterpret_cast<const uint4*>(p);
    float v[8];
    float s = 0.f, s2 = 0.f;
    #pragma unroll
    for (int q = 0; q < 4; q++) {
        float2 f = __half22float2(hv[q]);
        v[q*2] = f.x; v[q*2+1] = f.y;
        s += f.x + f.y;
        s2 = fmaf(f.x, f.x, fmaf(f.y, f.y, s2));
    }
    #pragma unroll
    for (int st = 16; st > 0; st >>= 1) {
        s  += __shfl_xor_sync(0xFFFFFFFF, s,  st);
        s2 += __shfl_xor_sync(0xFFFFFFFF, s2, st);
    }
    if (lane == 0) { red[w*2] = s; red[w*2+1] = s2; }
    __syncthreads();
    float ts  = red[0] + red[2] + red[4] + red[6];
    float ts2 = red[1] + red[3] + red[5] + red[7];
    float mu = ts * (1.f / HID);
    float var = ts2 * (1.f / HID) - mu * mu;
    float rstd = rsqrtf(var + EPS);

    float4 g0 = *reinterpret_cast<const float4*>(g + t * 8);
    float4 g1 = *reinterpret_cast<const float4*>(g + t * 8 + 4);
    float4 b0 = *reinterpret_cast<const float4*>(beta + t * 8);
    float4 b1 = *reinterpret_cast<const float4*>(beta + t * 8 + 4);
    float gv[8] = {g0.x, g0.y, g0.z, g0.w, g1.x, g1.y, g1.z, g1.w};
    float bv[8] = {b0.x, b0.y, b0.z, b0.w, b1.x, b1.y, b1.z, b1.w};

    __half2 p1[4], p2[4], p3[4];
    #pragma unroll
    for (int j = 0; j < 4; j++) {
        float ya = (v[2*j]   - mu) * rstd * gv[2*j]   + bv[2*j];
        float yb = (v[2*j+1] - mu) * rstd * gv[2*j+1] + bv[2*j+1];
        ya = 0.5f * ya * (1.f + erff(ya * 0.70710678118654752f));
        yb = 0.5f * yb * (1.f + erff(yb * 0.70710678118654752f));
        float ya2 = ya * ya, yb2 = yb * yb;
        p1[j] = __half2(__float2half_rn(ya),      __float2half_rn(yb));
        p2[j] = __half2(__float2half_rn(ya2),     __float2half_rn(yb2));
        p3[j] = __half2(__float2half_rn(ya2*ya),  __float2half_rn(yb2*yb));
    }
    __half* Ap = g_A3b + (size_t)blockIdx.x * 3072 + t * 8;
    *reinterpret_cast<uint4*>(Ap)        = *reinterpret_cast<uint4*>(p1);
    *reinterpret_cast<uint4*>(Ap + 1024) = *reinterpret_cast<uint4*>(p2);
    *reinterpret_cast<uint4*>(Ap + 2048) = *reinterpret_cast<uint4*>(p3);
}

// ---------------- fused KAN GEMM via fp16 mma.sync (persistent tiles) ----------------
__device__ __forceinline__ void load_stage_kan(const __half* A3, const __half* B3,
                                               int N, int m0, int n0, int kt,
                                               uint32_t bufA, uint32_t bufB, int tid) {
    int k0 = kt * KC;
    #pragma unroll
    for (int i = 0; i < 6; i++) {
        int id = tid + i * 256;
        int c = id & 3;
        int m = (id >> 2) & 127;
        int pl = id >> 9;
        const void* gp = (const void*)(A3 + (size_t)(m0 + m) * 3072 + pl * 1024 + k0 + c * 8);
        uint32_t sp = bufA + pl * 8192 + m * 64 + ((uint32_t)(c ^ ((m >> 1) & 3)) << 4);
        asm volatile("cp.async.cg.shared.global [%0], [%1], 16;" :: "r"(sp), "l"(gp));
    }
    #pragma unroll
    for (int i = 0; i < 6; i++) {
        int id = tid + i * 256;
        int c = id & 3;
        int n = (id >> 2) & 127;
        int pl = id >> 9;
        const void* gp = (const void*)(B3 + (size_t)pl * N * 1024 + (size_t)(n0 + n) * 1024 + k0 + c * 8);
        uint32_t sp = bufB + pl * 8192 + n * 64 + ((uint32_t)(c ^ ((n >> 1) & 3)) << 4);
        asm volatile("cp.async.cg.shared.global [%0], [%1], 16;" :: "r"(sp), "l"(gp));
    }
}

template<int STAGE>
__global__ void __launch_bounds__(256, 2) gemm_kan_mma() {
    const int N      = (STAGE == 1) ? HID : OUTC;
    const __half* A3 = (STAGE == 1) ? g_A3a : g_A3b;
    const __half* B3 = (STAGE == 1) ? g_B3a : g_B3b;
    const float* c0v = (STAGE == 1) ? g_c01 : g_c02;
    __half* C        = (STAGE == 1) ? g_h1h : g_h2h;
    const int nx     = N / 128;
    const int ntiles = (MTOT / 128) * nx;

    extern __shared__ char smem[];
    uint32_t sb = smem_u32(smem);
    int tid = threadIdx.x, lane = tid & 31, w = tid >> 5;
    int wm = w >> 1, wn = w & 1;

    uint32_t offB[8];
    {
        int c = lane >> 3;
        int rr = lane & 7;
        #pragma unroll
        for (int t = 0; t < 8; t++) {
            int r = wn * 64 + t * 8 + rr;
            offB[t] = (uint32_t)r * 64 + ((uint32_t)(c ^ ((r >> 1) & 3)) << 4);
        }
    }
    int hiA = lane >> 4;
    uint32_t aOff[2]; int aSw[2];
    #pragma unroll
    for (int s = 0; s < 2; s++) {
        int r = wm * 32 + s * 16 + (lane & 15);
        aOff[s] = (uint32_t)r * 64; aSw[s] = (r >> 1) & 3;
    }

    for (int tile = blockIdx.x; tile < ntiles; tile += gridDim.x) {
        int m0 = (tile / nx) * 128;
        int n0 = (tile % nx) * 128;

        float acc[2][8][4] = {};

        load_stage_kan(A3, B3, N, m0, n0, 0, sb, sb + A_ST, tid);
        asm volatile("cp.async.commit_group;" ::: "memory");
        load_stage_kan(A3, B3, N, m0, n0, 1, sb + STG, sb + STG + A_ST, tid);
        asm volatile("cp.async.commit_group;" ::: "memory");

        for (int kt = 0; kt < NK; kt++) {
            asm volatile("cp.async.wait_group 1;" ::: "memory");
            __syncthreads();

            uint32_t bufA = sb + (uint32_t)(kt & 1) * STG;
            uint32_t bufB = bufA + A_ST;

            #pragma unroll
            for (int o = 0; o < 3; o++) {
                uint32_t bq[8][4];
                #pragma unroll
                for (int t = 0; t < 8; t++)
                    LDSM_X4(bq[t], bufB + o * 8192 + offB[t]);
                #pragma unroll
                for (int kk = 0; kk < 2; kk++) {
                    #pragma unroll
                    for (int s = 0; s < 2; s++) {
                        uint32_t ah[4];
                        uint32_t base = bufA + o * 8192 + aOff[s];
                        LDSM_X4(ah, base + ((uint32_t)((kk * 2 + hiA) ^ aSw[s]) << 4));
                        #pragma unroll
                        for (int t = 0; t < 8; t++)
                            MMA16816(acc[s][t], ah, &bq[t][kk * 2]);
                    }
                }
            }
            __syncthreads();
            int j = kt + 2;
            if (j < NK)
                load_stage_kan(A3, B3, N, m0, n0, j, sb + (uint32_t)(kt & 1) * STG,
                               sb + (uint32_t)(kt & 1) * STG + A_ST, tid);
            asm volatile("cp.async.commit_group;" ::: "memory");
        }

        #pragma unroll
        for (int t = 0; t < 8; t++) {
            int col = n0 + wn * 64 + t * 8 + (lane & 3) * 2;
            float c0a = c0v[col], c0b = c0v[col + 1];
            #pragma unroll
            for (int s = 0; s < 2; s++) {
                int r0 = m0 + wm * 32 + s * 16 + (lane >> 2);
                __half2 v0 = __half2(__float2half_rn(acc[s][t][0] + c0a),
                                     __float2half_rn(acc[s][t][1] + c0b));
                __half2 v1 = __half2(__float2half_rn(acc[s][t][2] + c0a),
                                     __float2half_rn(acc[s][t][3] + c0b));
                *reinterpret_cast<__half2*>(C + (size_t)r0 * N + col) = v0;
                *reinterpret_cast<__half2*>(C + (size_t)(r0 + 8) * N + col) = v1;
            }
        }
        __syncthreads();   // all warps done with smem before next tile's prologue
    }
}

// ---------------- fused LN2 + partial mean over L (reads fp16 h2) ----------------
__global__ void ln2_reduce_kernel(const float* __restrict__ g, const float* __restrict__ beta) {
    __shared__ float part[8][OUTC];
    int seg = blockIdx.x, b = blockIdx.y;
    int lane = threadIdx.x & 31, w = threadIdx.x >> 5;
    int colb = lane * 16;

    float gv[16], bv[16];
    #pragma unroll
    for (int q = 0; q < 4; q++) {
        float4 t1 = *reinterpret_cast<const float4*>(g + colb + q * 4);
        float4 t2 = *reinterpret_cast<const float4*>(beta + colb + q * 4);
        gv[q*4+0]=t1.x; gv[q*4+1]=t1.y; gv[q*4+2]=t1.z; gv[q*4+3]=t1.w;
        bv[q*4+0]=t2.x; bv[q*4+1]=t2.y; bv[q*4+2]=t2.z; bv[q*4+3]=t2.w;
    }
    float acc[16];
    #pragma unroll
    for (int j = 0; j < 16; j++) acc[j] = 0.f;

    for (int i = 0; i < 16; i++) {
        int l = seg * 128 + w * 16 + i;
        const __half* row = g_h2h + ((size_t)b * LEN + l) * OUTC + colb;
        __half2 hv[8];
        *reinterpret_cast<uint4*>(hv)     = *reinterpret_cast<const uint4*>(row);
        *reinterpret_cast<uint4*>(hv + 4) = *reinterpret_cast<const uint4*>(row + 8);
        float v[16];
        float s = 0.f;
        #pragma unroll
        for (int q = 0; q < 8; q++) {
            float2 f = __half22float2(hv[q]);
            v[q*2] = f.x; v[q*2+1] = f.y;
            s += f.x + f.y;
        }
        #pragma unroll
        for (int st = 16; st > 0; st >>= 1) s += __shfl_xor_sync(0xFFFFFFFF, s, st);
        float mu = s * (1.f / OUTC);
        float s2 = 0.f;
        #pragma unroll
        for (int j = 0; j < 16; j++) { float d = v[j] - mu; s2 += d * d; }
        #pragma unroll
        for (int st = 16; st > 0; st >>= 1) s2 += __shfl_xor_sync(0xFFFFFFFF, s2, st);
        float rstd = rsqrtf(s2 * (1.f / OUTC) + EPS);
        #pragma unroll
        for (int j = 0; j < 16; j++)
            acc[j] += (v[j] - mu) * rstd * gv[j] + bv[j];
    }
    #pragma unroll
    for (int j = 0; j < 16; j++) part[w][colb + j] = acc[j];
    __syncthreads();
    int col = threadIdx.x;
    #pragma unroll
    for (int q = 0; q < 2; q++) {
        int cc = col + q * 256;
        float s = 0.f;
        #pragma unroll
        for (int ww = 0; ww < 8; ww++) s += part[ww][cc];
        g_part[((size_t)b * 8 + seg) * OUTC + cc] = s;
    }
}

__global__ void reduce2_kernel(float* __restrict__ out) {
    int b = blockIdx.x, o = threadIdx.x;
    const float* p = g_part + (size_t)b * 8 * OUTC + o;
    float s = 0.f;
    #pragma unroll
    for (int seg = 0; seg < 8; seg++) s += p[(size_t)seg * OUTC];
    out[b * OUTC + o] = s * (1.f / LEN);
}

// ---------------- launch ----------------
extern "C" void kernel_launch(void* const* d_in, const int* in_sizes, int n_in,
                              void* d_out, int out_size) {
    const float* x       = (const float*)d_in[0];
    const float* W_in    = (const float*)d_in[1];
    const float* b_in    = (const float*)d_in[2];
    const float* coeffs1 = (const float*)d_in[3];
    const float* bias1   = (const float*)d_in[4];
    const float* g1      = (const float*)d_in[5];
    const float* beta1   = (const float*)d_in[6];
    const float* coeffs2 = (const float*)d_in[7];
    const float* bias2   = (const float*)d_in[8];
    const float* g2      = (const float*)d_in[9];
    const float* beta2   = (const float*)d_in[10];
    float* out = (float*)d_out;

    cudaFuncSetAttribute(gemm_kan_mma<1>, cudaFuncAttributeMaxDynamicSharedMemorySize, SMEM_GEMM);
    cudaFuncSetAttribute(gemm_kan_mma<2>, cudaFuncAttributeMaxDynamicSharedMemorySize, SMEM_GEMM);
    cudaFuncSetAttribute(gemm_proj_tc, cudaFuncAttributeMaxDynamicSharedMemorySize, PROJ_SMEM);

    prep_kernel<<<128 + 8 + HID + OUTC, 256>>>(x, W_in, coeffs1, bias1, coeffs2, bias2);

    gemm_proj_tc<<<dim3(HID / 128, MTOT / 128), 256, PROJ_SMEM>>>(b_in);
    gemm_kan_mma<1><<<PERSIST_CTAS, 256, SMEM_GEMM>>>();
    ln_gelu_split_kernel<<<MTOT, 128>>>(g1, beta1);
    gemm_kan_mma<2><<<PERSIST_CTAS, 256, SMEM_GEMM>>>();
    ln2_reduce_kernel<<<dim3(8, BATCH), 256>>>(g2, beta2);
    reduce2_kernel<<<BATCH, OUTC>>>(out);
}

// round 17
// speedup vs baseline: 1.0443x; 1.0443x over previous
#include <cuda_runtime.h>
#include <cuda_fp16.h>
#include <cstdint>
#include <math.h>

#define BATCH 16
#define CIN   64
#define LEN   1024
#define HID   1024
#define OUTC  512
#define EPS   1e-5f
#define MTOT  (BATCH*LEN)   // 16384

// KAN GEMM tiling (R9/R15 best): CTA 128x128, KC=32, 2-stage, 2 CTAs/SM
#define KC     32
#define NK     (HID/KC)      // 32
#define A_ST   24576
#define B_ST   24576
#define STG    (A_ST + B_ST) // 49152
#define SMEM_GEMM (2*STG)    // 98304
#define PROJ_SMEM 67584
#define PRS 132

// ---------------- scratch ----------------
__device__ __align__(16)  __half g_h1h[MTOT*HID];
__device__ __align__(16)  __half g_h2h[MTOT*OUTC];
__device__ __align__(128) __half g_A3a[(size_t)MTOT*3072];
__device__ __align__(128) __half g_A3b[(size_t)MTOT*3072];
__device__ __align__(128) __half g_B3a[(size_t)3*HID*1024];
__device__ __align__(128) __half g_B3b[(size_t)3*OUTC*1024];
__device__ __align__(128) __half g_xh[(size_t)MTOT*64];
__device__ __align__(128) __half g_wh[(size_t)HID*64];
__device__ float g_c01[HID];
__device__ float g_c02[OUTC];
__device__ float g_part[BATCH*16*OUTC];

// ---------------- helpers ----------------
__device__ __forceinline__ uint32_t smem_u32(const void* p) {
    uint32_t a;
    asm("{ .reg .u64 t; cvta.to.shared.u64 t, %1; cvt.u32.u64 %0, t; }" : "=r"(a) : "l"(p));
    return a;
}
__device__ __forceinline__ float tanh_fast(float x) {
    float r;
    asm("tanh.approx.f32 %0, %1;" : "=f"(r) : "f"(x));
    return r;
}

#define LDSM_X4(r, addr) \
    asm volatile("ldmatrix.sync.aligned.m8n8.x4.shared.b16 {%0,%1,%2,%3}, [%4];" \
        : "=r"((r)[0]), "=r"((r)[1]), "=r"((r)[2]), "=r"((r)[3]) : "r"(addr))
#define MMA16816(d, a, b) \
    asm volatile("mma.sync.aligned.m16n8k16.row.col.f32.f16.f16.f32 " \
        "{%0,%1,%2,%3}, {%4,%5,%6,%7}, {%8,%9}, {%0,%1,%2,%3};" \
        : "+f"((d)[0]), "+f"((d)[1]), "+f"((d)[2]), "+f"((d)[3]) \
        : "r"((a)[0]), "r"((a)[1]), "r"((a)[2]), "r"((a)[3]), "r"((b)[0]), "r"((b)[1]))

// ---------------- fused prep: xconv | wconv | repackB1 | repackB2 ----------------
__global__ void prep_kernel(const float* __restrict__ x, const float* __restrict__ W,
                            const float* __restrict__ coeffs1, const float* __restrict__ bias1,
                            const float* __restrict__ coeffs2, const float* __restrict__ bias2) {
    __shared__ __align__(16) char sbuf[64 * 129 * 4];
    int blk = blockIdx.x;
    int tid = threadIdx.x;

    if (blk < 128) {                         // xconv
        float (*tile)[129] = reinterpret_cast<float(*)[129]>(sbuf);
        int b = blk >> 3, l0 = (blk & 7) * 128;
        #pragma unroll
        for (int i = 0; i < 32; i++) {
            int idx = tid + i * 256;
            int c = idx >> 7, l = idx & 127;
            tile[c][l] = x[((size_t)b * CIN + c) * LEN + l0 + l];
        }
        __syncthreads();
        #pragma unroll
        for (int i = 0; i < 4; i++) {
            int idx = tid + i * 256;
            int l = idx >> 3, q = idx & 7;
            __half2 h[4];
            #pragma unroll
            for (int j = 0; j < 4; j++) {
                int c = q * 8 + j * 2;
                h[j] = __half2(__float2half_rn(tile[c][l]), __float2half_rn(tile[c + 1][l]));
            }
            *reinterpret_cast<uint4*>(g_xh + ((size_t)(b * LEN + l0 + l)) * 64 + q * 8) =
                *reinterpret_cast<uint4*>(h);
        }
    } else if (blk < 136) {                  // wconv
        float (*tile)[129] = reinterpret_cast<float(*)[129]>(sbuf);
        int n0 = (blk - 128) * 128;
        #pragma unroll
        for (int i = 0; i < 32; i++) {
            int idx = tid + i * 256;
            int k = idx >> 7, n = idx & 127;
            tile[k][n] = W[(size_t)k * HID + n0 + n];
        }
        __syncthreads();
        #pragma unroll
        for (int i = 0; i < 4; i++) {
            int idx = tid + i * 256;
            int n = idx >> 3, q = idx & 7;
            __half2 h[4];
            #pragma unroll
            for (int j = 0; j < 4; j++) {
                int k = q * 8 + j * 2;
                h[j] = __half2(__float2half_rn(tile[k][n]), __float2half_rn(tile[k + 1][n]));
            }
            *reinterpret_cast<uint4*>(g_wh + ((size_t)(n0 + n)) * 64 + q * 8) =
                *reinterpret_cast<uint4*>(h);
        }
    } else {                                 // repackB
        int o; int N; __half* B3; float* c0;
        const float* coeffs; const float* bias;
        if (blk < 136 + HID) {
            o = blk - 136;        N = HID;  B3 = g_B3a; c0 = g_c01; coeffs = coeffs1; bias = bias1;
        } else {
            o = blk - 136 - HID;  N = OUTC; B3 = g_B3b; c0 = g_c02; coeffs = coeffs2; bias = bias2;
        }
        float* red = reinterpret_cast<float*>(sbuf);
        float s = 0.f;
        #pragma unroll
        for (int it = 0; it < 4; it++) {
            int c = tid + it * 256;
            float4 v = *reinterpret_cast<const float4*>(coeffs + ((size_t)o * HID + c) * 4);
            s += v.x;
            size_t base = (size_t)o * 1024 + c;
            size_t ps = (size_t)N * 1024;
            B3[0*ps + base] = __float2half_rn(v.y);
            B3[1*ps + base] = __float2half_rn(v.z);
            B3[2*ps + base] = __float2half_rn(v.w);
        }
        red[tid] = s; __syncthreads();
        #pragma unroll
        for (int st = 128; st > 0; st >>= 1) {
            if (tid < st) red[tid] += red[tid + st];
            __syncthreads();
        }
        if (tid == 0) c0[o] = red[0] + bias[o];
    }
}

// ---------------- projection GEMM on tensor cores + staged coalesced split ----------------
__global__ void __launch_bounds__(256, 2) gemm_proj_tc(const float* __restrict__ bias) {
    extern __shared__ char smem[];
    uint32_t sA = smem_u32(smem);
    uint32_t sB = sA + 16384;
    int tid = threadIdx.x, lane = tid & 31, w = tid >> 5;
    int wm = w >> 1, wn = w & 1;
    int m0 = blockIdx.y * 128, n0 = blockIdx.x * 128;

    #pragma unroll
    for (int i = 0; i < 4; i++) {
        int idx = tid + i * 256;
        int row = idx >> 3, ch = idx & 7;
        const void* gp = (const void*)(g_xh + (size_t)(m0 + row) * 64 + ch * 8);
        uint32_t sp = sA + row * 128 + ((uint32_t)(ch ^ (row & 7)) << 4);
        asm volatile("cp.async.cg.shared.global [%0], [%1], 16;" :: "r"(sp), "l"(gp));
    }
    #pragma unroll
    for (int i = 0; i < 4; i++) {
        int idx = tid + i * 256;
        int row = idx >> 3, ch = idx & 7;
        const void* gp = (const void*)(g_wh + (size_t)(n0 + row) * 64 + ch * 8);
        uint32_t sp = sB + row * 128 + ((uint32_t)(ch ^ (row & 7)) << 4);
        asm volatile("cp.async.cg.shared.global [%0], [%1], 16;" :: "r"(sp), "l"(gp));
    }
    asm volatile("cp.async.commit_group;" ::: "memory");
    asm volatile("cp.async.wait_group 0;" ::: "memory");
    __syncthreads();

    float acc[2][8][4] = {};
    int hiA = lane >> 4;
    uint32_t aOff[2]; int aSw[2];
    #pragma unroll
    for (int s = 0; s < 2; s++) {
        int r = wm * 32 + s * 16 + (lane & 15);
        aOff[s] = (uint32_t)r * 128; aSw[s] = r & 7;
    }
    uint32_t offB[2][8];
    #pragma unroll
    for (int grp = 0; grp < 2; grp++) {
        int c = (lane >> 3) + grp * 4;
        int rr = lane & 7;
        #pragma unroll
        for (int t = 0; t < 8; t++) {
            int r = wn * 64 + t * 8 + rr;
            offB[grp][t] = (uint32_t)r * 128 + ((uint32_t)(c ^ (r & 7)) << 4);
        }
    }

    #pragma unroll
    for (int grp = 0; grp < 2; grp++) {
        uint32_t bq[8][4];
        #pragma unroll
        for (int t = 0; t < 8; t++)
            LDSM_X4(bq[t], sB + offB[grp][t]);
        #pragma unroll
        for (int kp = 0; kp < 2; kp++) {
            int kk = grp * 2 + kp;
            #pragma unroll
            for (int s = 0; s < 2; s++) {
                uint32_t ah[4];
                LDSM_X4(ah, sA + aOff[s] + ((uint32_t)((kk * 2 + hiA) ^ aSw[s]) << 4));
                #pragma unroll
                for (int t = 0; t < 8; t++)
                    MMA16816(acc[s][t], ah, &bq[t][kp * 2]);
            }
        }
    }

    __syncthreads();
    float* tile = reinterpret_cast<float*>(smem);
    #pragma unroll
    for (int t = 0; t < 8; t++) {
        int col = wn * 64 + t * 8 + (lane & 3) * 2;
        #pragma unroll
        for (int s = 0; s < 2; s++) {
            int r0 = wm * 32 + s * 16 + (lane >> 2);
            *reinterpret_cast<float2*>(tile + (size_t)r0 * PRS + col) =
                make_float2(acc[s][t][0], acc[s][t][1]);
            *reinterpret_cast<float2*>(tile + (size_t)(r0 + 8) * PRS + col) =
                make_float2(acc[s][t][2], acc[s][t][3]);
        }
    }
    __syncthreads();

    int row = tid >> 1, half = tid & 1;
    const float* src = tile + (size_t)row * PRS + half * 64;
    const float* bsrc = bias + n0 + half * 64;
    __half* dst = g_A3a + (size_t)(m0 + row) * 3072 + n0 + half * 64;
    #pragma unroll
    for (int q = 0; q < 8; q++) {
        float4 v0 = *reinterpret_cast<const float4*>(src + q * 8);
        float4 v1 = *reinterpret_cast<const float4*>(src + q * 8 + 4);
        float4 b0 = *reinterpret_cast<const float4*>(bsrc + q * 8);
        float4 b1 = *reinterpret_cast<const float4*>(bsrc + q * 8 + 4);
        float hv[8] = {v0.x + b0.x, v0.y + b0.y, v0.z + b0.z, v0.w + b0.w,
                       v1.x + b1.x, v1.y + b1.y, v1.z + b1.z, v1.w + b1.w};
        __half2 p1[4], p2[4], p3[4];
        #pragma unroll
        for (int j = 0; j < 4; j++) {
            float a = hv[2*j], b = hv[2*j+1];
            float a2 = a * a, b2 = b * b;
            p1[j] = __half2(__float2half_rn(a),     __float2half_rn(b));
            p2[j] = __half2(__float2half_rn(a2),    __float2half_rn(b2));
            p3[j] = __half2(__float2half_rn(a2*a),  __float2half_rn(b2*b));
        }
        *reinterpret_cast<uint4*>(dst + q * 8)        = *reinterpret_cast<uint4*>(p1);
        *reinterpret_cast<uint4*>(dst + 1024 + q * 8) = *reinterpret_cast<uint4*>(p2);
        *reinterpret_cast<uint4*>(dst + 2048 + q * 8) = *reinterpret_cast<uint4*>(p3);
    }
}

// ---------------- LN + tanh-GELU + fp16 power split (shfl LN, 128 thr/row) ----------------
__global__ void __launch_bounds__(128) ln_gelu_split_kernel(const float* __restrict__ g,
                                                            const float* __restrict__ beta) {
    __shared__ float red[8];
    int t = threadIdx.x;
    int lane = t & 31, w = t >> 5;
    const __half* p = g_h1h + (size_t)blockIdx.x * HID + t * 8;
    __half2 hv[4];
    *reinterpret_cast<uint4*>(hv) = *reinterpret_cast<const uint4*>(p);
    float v[8];
    float s = 0.f, s2 = 0.f;
    #pragma unroll
    for (int q = 0; q < 4; q++) {
        float2 f = __half22float2(hv[q]);
        v[q*2] = f.x; v[q*2+1] = f.y;
        s += f.x + f.y;
        s2 = fmaf(f.x, f.x, fmaf(f.y, f.y, s2));
    }
    #pragma unroll
    for (int st = 16; st > 0; st >>= 1) {
        s  += __shfl_xor_sync(0xFFFFFFFF, s,  st);
        s2 += __shfl_xor_sync(0xFFFFFFFF, s2, st);
    }
    if (lane == 0) { red[w*2] = s; red[w*2+1] = s2; }
    __syncthreads();
    float ts  = red[0] + red[2] + red[4] + red[6];
    float ts2 = red[1] + red[3] + red[5] + red[7];
    float mu = ts * (1.f / HID);
    float var = ts2 * (1.f / HID) - mu * mu;
    float rstd = rsqrtf(var + EPS);

    float4 g0 = *reinterpret_cast<const float4*>(g + t * 8);
    float4 g1 = *reinterpret_cast<const float4*>(g + t * 8 + 4);
    float4 b0 = *reinterpret_cast<const float4*>(beta + t * 8);
    float4 b1 = *reinterpret_cast<const float4*>(beta + t * 8 + 4);
    float gv[8] = {g0.x, g0.y, g0.z, g0.w, g1.x, g1.y, g1.z, g1.w};
    float bv[8] = {b0.x, b0.y, b0.z, b0.w, b1.x, b1.y, b1.z, b1.w};

    __half2 p1[4], p2[4], p3[4];
    #pragma unroll
    for (int j = 0; j < 4; j++) {
        float ya = (v[2*j]   - mu) * rstd * gv[2*j]   + bv[2*j];
        float yb = (v[2*j+1] - mu) * rstd * gv[2*j+1] + bv[2*j+1];
        // gelu via tanh: 0.5*y*(1+tanh(0.79788456*(y + 0.044715*y^3)))
        float ta = tanh_fast(0.7978845608f * fmaf(0.044715f * ya * ya, ya, ya));
        float tb = tanh_fast(0.7978845608f * fmaf(0.044715f * yb * yb, yb, yb));
        ya = 0.5f * ya * (1.f + ta);
        yb = 0.5f * yb * (1.f + tb);
        float ya2 = ya * ya, yb2 = yb * yb;
        p1[j] = __half2(__float2half_rn(ya),      __float2half_rn(yb));
        p2[j] = __half2(__float2half_rn(ya2),     __float2half_rn(yb2));
        p3[j] = __half2(__float2half_rn(ya2*ya),  __float2half_rn(yb2*yb));
    }
    __half* Ap = g_A3b + (size_t)blockIdx.x * 3072 + t * 8;
    *reinterpret_cast<uint4*>(Ap)        = *reinterpret_cast<uint4*>(p1);
    *reinterpret_cast<uint4*>(Ap + 1024) = *reinterpret_cast<uint4*>(p2);
    *reinterpret_cast<uint4*>(Ap + 2048) = *reinterpret_cast<uint4*>(p3);
}

// ---------------- fused KAN GEMM via fp16 mma.sync (R15 config; fp16 output) ----------------
__device__ __forceinline__ void load_stage_kan(const __half* A3, const __half* B3,
                                               int N, int m0, int n0, int kt,
                                               uint32_t bufA, uint32_t bufB, int tid) {
    int k0 = kt * KC;
    #pragma unroll
    for (int i = 0; i < 6; i++) {
        int id = tid + i * 256;
        int c = id & 3;
        int m = (id >> 2) & 127;
        int pl = id >> 9;
        const void* gp = (const void*)(A3 + (size_t)(m0 + m) * 3072 + pl * 1024 + k0 + c * 8);
        uint32_t sp = bufA + pl * 8192 + m * 64 + ((uint32_t)(c ^ ((m >> 1) & 3)) << 4);
        asm volatile("cp.async.cg.shared.global [%0], [%1], 16;" :: "r"(sp), "l"(gp));
    }
    #pragma unroll
    for (int i = 0; i < 6; i++) {
        int id = tid + i * 256;
        int c = id & 3;
        int n = (id >> 2) & 127;
        int pl = id >> 9;
        const void* gp = (const void*)(B3 + (size_t)pl * N * 1024 + (size_t)(n0 + n) * 1024 + k0 + c * 8);
        uint32_t sp = bufB + pl * 8192 + n * 64 + ((uint32_t)(c ^ ((n >> 1) & 3)) << 4);
        asm volatile("cp.async.cg.shared.global [%0], [%1], 16;" :: "r"(sp), "l"(gp));
    }
}

template<int STAGE>
__global__ void __launch_bounds__(256, 2) gemm_kan_mma() {
    const int N      = (STAGE == 1) ? HID : OUTC;
    const __half* A3 = (STAGE == 1) ? g_A3a : g_A3b;
    const __half* B3 = (STAGE == 1) ? g_B3a : g_B3b;
    const float* c0v = (STAGE == 1) ? g_c01 : g_c02;
    __half* C        = (STAGE == 1) ? g_h1h : g_h2h;

    extern __shared__ char smem[];
    uint32_t sb = smem_u32(smem);
    int tid = threadIdx.x, lane = tid & 31, w = tid >> 5;
    int wm = w >> 1, wn = w & 1;
    int m0 = blockIdx.y * 128, n0 = blockIdx.x * 128;

    float acc[2][8][4] = {};

    uint32_t offB[8];
    {
        int c = lane >> 3;
        int rr = lane & 7;
        #pragma unroll
        for (int t = 0; t < 8; t++) {
            int r = wn * 64 + t * 8 + rr;
            offB[t] = (uint32_t)r * 64 + ((uint32_t)(c ^ ((r >> 1) & 3)) << 4);
        }
    }
    int hiA = lane >> 4;
    uint32_t aOff[2]; int aSw[2];
    #pragma unroll
    for (int s = 0; s < 2; s++) {
        int r = wm * 32 + s * 16 + (lane & 15);
        aOff[s] = (uint32_t)r * 64; aSw[s] = (r >> 1) & 3;
    }

    load_stage_kan(A3, B3, N, m0, n0, 0, sb, sb + A_ST, tid);
    asm volatile("cp.async.commit_group;" ::: "memory");
    load_stage_kan(A3, B3, N, m0, n0, 1, sb + STG, sb + STG + A_ST, tid);
    asm volatile("cp.async.commit_group;" ::: "memory");

    for (int kt = 0; kt < NK; kt++) {
        asm volatile("cp.async.wait_group 1;" ::: "memory");
        __syncthreads();

        uint32_t bufA = sb + (uint32_t)(kt & 1) * STG;
        uint32_t bufB = bufA + A_ST;

        #pragma unroll
        for (int o = 0; o < 3; o++) {
            uint32_t bq[8][4];
            #pragma unroll
            for (int t = 0; t < 8; t++)
                LDSM_X4(bq[t], bufB + o * 8192 + offB[t]);
            #pragma unroll
            for (int kk = 0; kk < 2; kk++) {
                #pragma unroll
                for (int s = 0; s < 2; s++) {
                    uint32_t ah[4];
                    uint32_t base = bufA + o * 8192 + aOff[s];
                    LDSM_X4(ah, base + ((uint32_t)((kk * 2 + hiA) ^ aSw[s]) << 4));
                    #pragma unroll
                    for (int t = 0; t < 8; t++)
                        MMA16816(acc[s][t], ah, &bq[t][kk * 2]);
                }
            }
        }
        __syncthreads();
        int j = kt + 2;
        if (j < NK)
            load_stage_kan(A3, B3, N, m0, n0, j, bufA, bufB, tid);
        asm volatile("cp.async.commit_group;" ::: "memory");
    }

    #pragma unroll
    for (int t = 0; t < 8; t++) {
        int col = n0 + wn * 64 + t * 8 + (lane & 3) * 2;
        float c0a = c0v[col], c0b = c0v[col + 1];
        #pragma unroll
        for (int s = 0; s < 2; s++) {
            int r0 = m0 + wm * 32 + s * 16 + (lane >> 2);
            __half2 v0 = __half2(__float2half_rn(acc[s][t][0] + c0a),
                                 __float2half_rn(acc[s][t][1] + c0b));
            __half2 v1 = __half2(__float2half_rn(acc[s][t][2] + c0a),
                                 __float2half_rn(acc[s][t][3] + c0b));
            *reinterpret_cast<__half2*>(C + (size_t)r0 * N + col) = v0;
            *reinterpret_cast<__half2*>(C + (size_t)(r0 + 8) * N + col) = v1;
        }
    }
}

// ---------------- fused LN2 + partial mean over L (16 segs; warp = 8 rows) ----------------
__global__ void ln2_reduce_kernel(const float* __restrict__ g, const float* __restrict__ beta) {
    __shared__ float part[8][OUTC];
    int seg = blockIdx.x, b = blockIdx.y;
    int lane = threadIdx.x & 31, w = threadIdx.x >> 5;
    int colb = lane * 16;

    float gv[16], bv[16];
    #pragma unroll
    for (int q = 0; q < 4; q++) {
        float4 t1 = *reinterpret_cast<const float4*>(g + colb + q * 4);
        float4 t2 = *reinterpret_cast<const float4*>(beta + colb + q * 4);
        gv[q*4+0]=t1.x; gv[q*4+1]=t1.y; gv[q*4+2]=t1.z; gv[q*4+3]=t1.w;
        bv[q*4+0]=t2.x; bv[q*4+1]=t2.y; bv[q*4+2]=t2.z; bv[q*4+3]=t2.w;
    }
    float acc[16];
    #pragma unroll
    for (int j = 0; j < 16; j++) acc[j] = 0.f;

    for (int i = 0; i < 8; i++) {
        int l = seg * 64 + w * 8 + i;
        const __half* row = g_h2h + ((size_t)b * LEN + l) * OUTC + colb;
        __half2 hv[8];
        *reinterpret_cast<uint4*>(hv)     = *reinterpret_cast<const uint4*>(row);
        *reinterpret_cast<uint4*>(hv + 4) = *reinterpret_cast<const uint4*>(row + 8);
        float v[16];
        float s = 0.f;
        #pragma unroll
        for (int q = 0; q < 8; q++) {
            float2 f = __half22float2(hv[q]);
            v[q*2] = f.x; v[q*2+1] = f.y;
            s += f.x + f.y;
        }
        #pragma unroll
        for (int st = 16; st > 0; st >>= 1) s += __shfl_xor_sync(0xFFFFFFFF, s, st);
        float mu = s * (1.f / OUTC);
        float s2 = 0.f;
        #pragma unroll
        for (int j = 0; j < 16; j++) { float d = v[j] - mu; s2 += d * d; }
        #pragma unroll
        for (int st = 16; st > 0; st >>= 1) s2 += __shfl_xor_sync(0xFFFFFFFF, s2, st);
        float rstd = rsqrtf(s2 * (1.f / OUTC) + EPS);
        #pragma unroll
        for (int j = 0; j < 16; j++)
            acc[j] += (v[j] - mu) * rstd * gv[j] + bv[j];
    }
    #pragma unroll
    for (int j = 0; j < 16; j++) part[w][colb + j] = acc[j];
    __syncthreads();
    int col = threadIdx.x;
    #pragma unroll
    for (int q = 0; q < 2; q++) {
        int cc = col + q * 256;
        float s = 0.f;
        #pragma unroll
        for (int ww = 0; ww < 8; ww++) s += part[ww][cc];
        g_part[((size_t)b * 16 + seg) * OUTC + cc] = s;
    }
}

__global__ void reduce2_kernel(float* __restrict__ out) {
    int b = blockIdx.x, o = threadIdx.x;
    const float* p = g_part + (size_t)b * 16 * OUTC + o;
    float s = 0.f;
    #pragma unroll
    for (int seg = 0; seg < 16; seg++) s += p[(size_t)seg * OUTC];
    out[b * OUTC + o] = s * (1.f / LEN);
}

// ---------------- launch ----------------
extern "C" void kernel_launch(void* const* d_in, const int* in_sizes, int n_in,
                              void* d_out, int out_size) {
    const float* x       = (const float*)d_in[0];
    const float* W_in    = (const float*)d_in[1];
    const float* b_in    = (const float*)d_in[2];
    const float* coeffs1 = (const float*)d_in[3];
    const float* bias1   = (const float*)d_in[4];
    const float* g1      = (const float*)d_in[5];
    const float* beta1   = (const float*)d_in[6];
    const float* coeffs2 = (const float*)d_in[7];
    const float* bias2   = (const float*)d_in[8];
    const float* g2      = (const float*)d_in[9];
    const float* beta2   = (const float*)d_in[10];
    float* out = (float*)d_out;

    cudaFuncSetAttribute(gemm_kan_mma<1>, cudaFuncAttributeMaxDynamicSharedMemorySize, SMEM_GEMM);
    cudaFuncSetAttribute(gemm_kan_mma<2>, cudaFuncAttributeMaxDynamicSharedMemorySize, SMEM_GEMM);
    cudaFuncSetAttribute(gemm_proj_tc, cudaFuncAttributeMaxDynamicSharedMemorySize, PROJ_SMEM);

    prep_kernel<<<128 + 8 + HID + OUTC, 256>>>(x, W_in, coeffs1, bias1, coeffs2, bias2);

    gemm_proj_tc<<<dim3(HID / 128, MTOT / 128), 256, PROJ_SMEM>>>(b_in);
    gemm_kan_mma<1><<<dim3(HID / 128, MTOT / 128), 256, SMEM_GEMM>>>();
    ln_gelu_split_kernel<<<MTOT, 128>>>(g1, beta1);
    gemm_kan_mma<2><<<dim3(OUTC / 128, MTOT / 128), 256, SMEM_GEMM>>>();
    ln2_reduce_kernel<<<dim3(16, BATCH), 256>>>(g2, beta2);
    reduce2_kernel<<<BATCH, OUTC>>>(out);
}